// round 6
// baseline (speedup 1.0000x reference)
#include <cuda_runtime.h>
#include <math.h>
#include <stdint.h>

#define T 1024
#define C 128
#define NB 16
#define LUP 523776          // T*(T-1)/2
#define NOUT 2046           // LUP / 256
#define LEAK 0.2f

// ---------------------------------------------------------------------------
// Device globals (scratch)
// ---------------------------------------------------------------------------
__device__ float g_up[(size_t)NB * LUP];   // packed upper-triangle distances
__device__ float g_xx[NB * T];             // row squared norms

// ---------------------------------------------------------------------------
// Helpers
// ---------------------------------------------------------------------------
__device__ __forceinline__ uint32_t to_tf32(float f) {
    uint32_t r;
    asm("cvt.rna.tf32.f32 %0, %1;" : "=r"(r) : "f"(f));
    return r;
}

__device__ __forceinline__ void mma_tf32(float* d, const uint32_t* a, const uint32_t* b) {
    asm volatile(
        "mma.sync.aligned.m16n8k8.row.col.f32.tf32.tf32.f32 "
        "{%0,%1,%2,%3}, {%4,%5,%6,%7}, {%8,%9}, {%0,%1,%2,%3};"
        : "+f"(d[0]), "+f"(d[1]), "+f"(d[2]), "+f"(d[3])
        : "r"(a[0]), "r"(a[1]), "r"(a[2]), "r"(a[3]),
          "r"(b[0]), "r"(b[1]));
}

__device__ __forceinline__ float lrelu(float v) {
    return fmaxf(v, LEAK * v);
}

// 8ch -> 8ch conv step on register inputs. W row layout: W[c*16 + ci*2 + k]
// (co, ci, k) row-major; loaded as 4x float4 per output channel.
__device__ __forceinline__ void layer8(const float* __restrict__ W,
                                       const float* __restrict__ B,
                                       const float* v0, const float* v1,
                                       float* o, bool act)
{
    #pragma unroll
    for (int c = 0; c < 8; ++c) {
        const float4* Wc = (const float4*)(W + c * 16);
        float4 wa = Wc[0], wb = Wc[1], wc = Wc[2], wd = Wc[3];
        float acc = B[c];
        acc = fmaf(wa.x, v0[0], acc); acc = fmaf(wa.y, v1[0], acc);
        acc = fmaf(wa.z, v0[1], acc); acc = fmaf(wa.w, v1[1], acc);
        acc = fmaf(wb.x, v0[2], acc); acc = fmaf(wb.y, v1[2], acc);
        acc = fmaf(wb.z, v0[3], acc); acc = fmaf(wb.w, v1[3], acc);
        acc = fmaf(wc.x, v0[4], acc); acc = fmaf(wc.y, v1[4], acc);
        acc = fmaf(wc.z, v0[5], acc); acc = fmaf(wc.w, v1[5], acc);
        acc = fmaf(wd.x, v0[6], acc); acc = fmaf(wd.y, v1[6], acc);
        acc = fmaf(wd.z, v0[7], acc); acc = fmaf(wd.w, v1[7], acc);
        o[c] = act ? lrelu(acc) : acc;
    }
}

// ---------------------------------------------------------------------------
// Kernel 1: xx[b][i] = sum_c x[b][i][c]^2.  One warp per row.
// ---------------------------------------------------------------------------
__global__ __launch_bounds__(256) void xx_kernel(const float* __restrict__ x) {
    int warp = (blockIdx.x * 256 + threadIdx.x) >> 5;
    int lane = threadIdx.x & 31;
    if (warp >= NB * T) return;
    const float4* row = (const float4*)(x + (size_t)warp * C);
    float4 v = row[lane];
    float s = v.x * v.x + v.y * v.y + v.z * v.z + v.w * v.w;
    #pragma unroll
    for (int o = 16; o; o >>= 1) s += __shfl_xor_sync(0xffffffffu, s, o);
    if (lane == 0) g_xx[warp] = s;
}

// ---------------------------------------------------------------------------
// Kernel 2: tf32 mma.sync Gram tiles -> packed sqrt distances.
// (verbatim from round-3 passing build)
// ---------------------------------------------------------------------------
#define AS_STRIDE 132
#define AS_BYTES  (128 * AS_STRIDE * 4)       // 67584
#define DIST_SMEM (2 * AS_BYTES)              // 135168

__global__ __launch_bounds__(256) void dist_kernel(const float* __restrict__ x) {
    extern __shared__ __align__(16) unsigned char sm[];
    uint32_t* As = (uint32_t*)sm;
    uint32_t* Bs = (uint32_t*)(sm + AS_BYTES);

    int tid = threadIdx.x;
    int wid = tid >> 5;
    int lane = tid & 31;
    int grp = lane >> 2;        // 0..7
    int tg  = lane & 3;         // 0..3

    int b = blockIdx.y;
    int t = blockIdx.x;
    int ti = 0, rem = t;
    while (rem >= 8 - ti) { rem -= 8 - ti; ++ti; }
    int tj = ti + rem;
    int i0 = ti * 128, j0 = tj * 128;

    const float* xb = x + (size_t)b * T * C;

    #pragma unroll
    for (int it = 0; it < 16; ++it) {
        int f4 = it * 256 + tid;
        int row = f4 >> 5, c4 = f4 & 31;
        float4 va = *(const float4*)(xb + (size_t)(i0 + row) * C + c4 * 4);
        uint4 ta = make_uint4(to_tf32(va.x), to_tf32(va.y), to_tf32(va.z), to_tf32(va.w));
        *(uint4*)&As[row * AS_STRIDE + c4 * 4] = ta;
        float4 vb = *(const float4*)(xb + (size_t)(j0 + row) * C + c4 * 4);
        uint4 tb = make_uint4(to_tf32(vb.x), to_tf32(vb.y), to_tf32(vb.z), to_tf32(vb.w));
        *(uint4*)&Bs[row * AS_STRIDE + c4 * 4] = tb;
    }
    __syncthreads();

    int warp_m = (wid >> 2) * 64;
    int warp_n = (wid & 3) * 32;

    float acc[4][4][4];
    #pragma unroll
    for (int e = 0; e < 4; ++e)
        #pragma unroll
        for (int f = 0; f < 4; ++f)
            #pragma unroll
            for (int q = 0; q < 4; ++q) acc[e][f][q] = 0.0f;

    int abase = (warp_m + grp) * AS_STRIDE + tg;
    int bbase = (warp_n + grp) * AS_STRIDE + tg;

    #pragma unroll 2
    for (int kb = 0; kb < 128; kb += 8) {
        uint32_t a[4][4], bf[4][2];
        #pragma unroll
        for (int e = 0; e < 4; ++e) {
            int r = abase + 16 * e * AS_STRIDE + kb;
            a[e][0] = As[r];
            a[e][1] = As[r + 8 * AS_STRIDE];
            a[e][2] = As[r + 4];
            a[e][3] = As[r + 8 * AS_STRIDE + 4];
        }
        #pragma unroll
        for (int f = 0; f < 4; ++f) {
            int r = bbase + 8 * f * AS_STRIDE + kb;
            bf[f][0] = Bs[r];
            bf[f][1] = Bs[r + 4];
        }
        #pragma unroll
        for (int e = 0; e < 4; ++e)
            #pragma unroll
            for (int f = 0; f < 4; ++f)
                mma_tf32(acc[e][f], a[e], bf[f]);
    }

    float xi[4][2], xj[4][2];
    #pragma unroll
    for (int e = 0; e < 4; ++e) {
        int il = warp_m + 16 * e + grp;
        xi[e][0] = g_xx[b * T + i0 + il];
        xi[e][1] = g_xx[b * T + i0 + il + 8];
    }
    #pragma unroll
    for (int f = 0; f < 4; ++f) {
        int jl = warp_n + 8 * f + 2 * tg;
        xj[f][0] = g_xx[b * T + j0 + jl];
        xj[f][1] = g_xx[b * T + j0 + jl + 1];
    }

    __syncthreads();
    float* S = (float*)sm;   // 128 x stride-129 staging

    #pragma unroll
    for (int e = 0; e < 4; ++e) {
        int il = warp_m + 16 * e + grp;
        #pragma unroll
        for (int f = 0; f < 4; ++f) {
            int jl = warp_n + 8 * f + 2 * tg;
            float d00 = fmaf(-2.0f, acc[e][f][0], xi[e][0] + xj[f][0]);
            float d01 = fmaf(-2.0f, acc[e][f][1], xi[e][0] + xj[f][1]);
            float d10 = fmaf(-2.0f, acc[e][f][2], xi[e][1] + xj[f][0]);
            float d11 = fmaf(-2.0f, acc[e][f][3], xi[e][1] + xj[f][1]);
            S[il * 129 + jl]           = sqrtf(fmaxf(d00, 0.0f));
            S[il * 129 + jl + 1]       = sqrtf(fmaxf(d01, 0.0f));
            S[(il + 8) * 129 + jl]     = sqrtf(fmaxf(d10, 0.0f));
            S[(il + 8) * 129 + jl + 1] = sqrtf(fmaxf(d11, 0.0f));
        }
    }
    __syncthreads();

    {
        long bbase2 = (long)b * LUP;
        #pragma unroll
        for (int q = tid; q < 128 * 128; q += 256) {
            int m = q >> 7, jj = q & 127;
            int i2 = i0 + m, j2 = j0 + jj;
            if (j2 > i2) {
                long ro = (long)i2 * (2 * T - 1 - i2) / 2 - i2 - 1;
                g_up[bbase2 + ro + j2] = S[m * 129 + jj];
            }
        }
    }
}

// ---------------------------------------------------------------------------
// Kernel 3 (v3): register-subtree conv.
// Block = 31 final outputs (2046 = 66*31). Each thread computes one full L3
// subtree (1 L3 <- 2 L2 <- 4 L1 <- 8 L0 <- 16 inputs) in registers: no smem
// activations, no barriers for 4 layers. Weights read as float4 broadcasts.
// Then a tiny 4-step smem tail for L4..L7.
// Smem floats: wgt [0,1024) | binp [1024, 8960) (7936; tail reuses region:
//   l4buf@1024 (1984), l5buf@3072 (992), l6buf@5120 (496)) | l3buf [8960,12928)
// ---------------------------------------------------------------------------
#define CV_WGT   0
#define CV_BINP  1024
#define CV_L4    1024
#define CV_L5    3072
#define CV_L6    5120
#define CV_L3    8960
#define CONV_SMEM ((8960 + 3968) * 4)     // 51712 bytes

// tail step: src/dst channel-inner in smem
__device__ __forceinline__ void tail_layer(const float* __restrict__ W,
                                           const float* __restrict__ B,
                                           const float* __restrict__ src,
                                           float* __restrict__ dst, int p)
{
    float4 a0 = *(const float4*)&src[16 * p];
    float4 a1 = *(const float4*)&src[16 * p + 4];
    float4 a2 = *(const float4*)&src[16 * p + 8];
    float4 a3 = *(const float4*)&src[16 * p + 12];
    float in0[8] = {a0.x, a0.y, a0.z, a0.w, a1.x, a1.y, a1.z, a1.w};
    float in1[8] = {a2.x, a2.y, a2.z, a2.w, a3.x, a3.y, a3.z, a3.w};
    float o[8];
    layer8(W, B, in0, in1, o, true);
    *(float4*)&dst[8 * p]     = make_float4(o[0], o[1], o[2], o[3]);
    *(float4*)&dst[8 * p + 4] = make_float4(o[4], o[5], o[6], o[7]);
}

__global__ __launch_bounds__(256) void conv_kernel(
    const float* __restrict__ w0, const float* __restrict__ b0,
    const float* __restrict__ w1, const float* __restrict__ b1,
    const float* __restrict__ w2, const float* __restrict__ b2,
    const float* __restrict__ w3, const float* __restrict__ b3,
    const float* __restrict__ w4, const float* __restrict__ b4,
    const float* __restrict__ w5, const float* __restrict__ b5,
    const float* __restrict__ w6, const float* __restrict__ b6,
    const float* __restrict__ w7, const float* __restrict__ b7,
    float* __restrict__ out)
{
    extern __shared__ __align__(16) float cs[];
    float* wgt   = cs + CV_WGT;
    float* binp  = cs + CV_BINP;
    float* l3buf = cs + CV_L3;
    float* l4buf = cs + CV_L4;
    float* l5buf = cs + CV_L5;
    float* l6buf = cs + CV_L6;

    int tid = threadIdx.x;
    int b   = blockIdx.y;
    int blk = blockIdx.x;        // 0..65

    // ---- stage weights ----
    if (tid < 128) {
        wgt[ 24 + tid] = w1[tid];
        wgt[152 + tid] = w2[tid];
        wgt[280 + tid] = w3[tid];
        wgt[408 + tid] = w4[tid];
        wgt[536 + tid] = w5[tid];
        wgt[664 + tid] = w6[tid];
    } else {
        int u = tid - 128;
        if (u < 16)       wgt[u]            = w0[u];
        else if (u < 24)  wgt[u]            = b0[u - 16];
        else if (u < 32)  wgt[792 + (u-24)] = b1[u-24];
        else if (u < 40)  wgt[800 + (u-32)] = b2[u-32];
        else if (u < 48)  wgt[808 + (u-40)] = b3[u-40];
        else if (u < 56)  wgt[816 + (u-48)] = b4[u-48];
        else if (u < 64)  wgt[824 + (u-56)] = b5[u-56];
        else if (u < 72)  wgt[832 + (u-64)] = b6[u-64];
        else if (u < 88)  wgt[840 + (u-72)] = w7[u-72];
        else if (u == 88) wgt[856]          = b7[0];
    }

    // ---- stage 7936 contiguous inputs (coalesced float4) ----
    {
        const float4* src = (const float4*)(g_up + (size_t)b * LUP + (size_t)blk * 7936);
        float4* dst = (float4*)binp;
        for (int q = tid; q < 1984; q += 256) dst[q] = src[q];
    }
    __syncthreads();

    // ---- phase A: one L3 subtree per thread, 496 positions in 2 iters ----
    #pragma unroll
    for (int it = 0; it < 2; ++it) {
        int p = tid + it * 256;
        if (p < 496) {
            float L2v[2][8];
            #pragma unroll
            for (int h2 = 0; h2 < 2; ++h2) {
                float L1v[2][8];
                #pragma unroll
                for (int h1 = 0; h1 < 2; ++h1) {
                    float4 u = *(const float4*)&binp[16 * p + h2 * 8 + h1 * 4];
                    float e0[8], e1[8];
                    #pragma unroll
                    for (int c = 0; c < 8; ++c) {
                        float2 w = *(const float2*)&wgt[2 * c];
                        float bc = wgt[16 + c];
                        e0[c] = lrelu(fmaf(w.x, u.x, fmaf(w.y, u.y, bc)));
                        e1[c] = lrelu(fmaf(w.x, u.z, fmaf(w.y, u.w, bc)));
                    }
                    layer8(wgt + 24, wgt + 792, e0, e1, L1v[h1], true);
                }
                layer8(wgt + 152, wgt + 800, L1v[0], L1v[1], L2v[h2], true);
            }
            float o3[8];
            layer8(wgt + 280, wgt + 808, L2v[0], L2v[1], o3, true);
            *(float4*)&l3buf[8 * p]     = make_float4(o3[0], o3[1], o3[2], o3[3]);
            *(float4*)&l3buf[8 * p + 4] = make_float4(o3[4], o3[5], o3[6], o3[7]);
        }
    }
    __syncthreads();

    // ---- tail: L4 (248), L5 (124), L6 (62), L7 (31) ----
    if (tid < 248) tail_layer(wgt + 408, wgt + 816, l3buf, l4buf, tid);
    __syncthreads();
    if (tid < 124) tail_layer(wgt + 536, wgt + 824, l4buf, l5buf, tid);
    __syncthreads();
    if (tid < 62)  tail_layer(wgt + 664, wgt + 832, l5buf, l6buf, tid);
    __syncthreads();
    if (tid < 31) {
        const float* s0 = l6buf + 16 * tid;
        const float4* Wc = (const float4*)(wgt + 840);
        float4 wa = Wc[0], wb = Wc[1], wc = Wc[2], wd = Wc[3];
        float acc = wgt[856];
        acc = fmaf(wa.x, s0[0], acc); acc = fmaf(wa.y, s0[8],  acc);
        acc = fmaf(wa.z, s0[1], acc); acc = fmaf(wa.w, s0[9],  acc);
        acc = fmaf(wb.x, s0[2], acc); acc = fmaf(wb.y, s0[10], acc);
        acc = fmaf(wb.z, s0[3], acc); acc = fmaf(wb.w, s0[11], acc);
        acc = fmaf(wc.x, s0[4], acc); acc = fmaf(wc.y, s0[12], acc);
        acc = fmaf(wc.z, s0[5], acc); acc = fmaf(wc.w, s0[13], acc);
        acc = fmaf(wd.x, s0[6], acc); acc = fmaf(wd.y, s0[14], acc);
        acc = fmaf(wd.z, s0[7], acc); acc = fmaf(wd.w, s0[15], acc);
        out[b * NOUT + blk * 31 + tid] = acc;
    }
}

// ---------------------------------------------------------------------------
extern "C" void kernel_launch(void* const* d_in, const int* in_sizes, int n_in,
                              void* d_out, int out_size) {
    const float* x = (const float*)d_in[0];
    const float* w[8];
    const float* bb[8];
    for (int i = 0; i < 8; ++i) {
        w[i]  = (const float*)d_in[1 + 2 * i];
        bb[i] = (const float*)d_in[2 + 2 * i];
    }
    float* out = (float*)d_out;

    cudaFuncSetAttribute(dist_kernel,
                         cudaFuncAttributeMaxDynamicSharedMemorySize, DIST_SMEM);
    cudaFuncSetAttribute(conv_kernel,
                         cudaFuncAttributeMaxDynamicSharedMemorySize, CONV_SMEM);

    xx_kernel<<<(NB * T) / 8, 256>>>(x);
    dist_kernel<<<dim3(36, NB), 256, DIST_SMEM>>>(x);
    conv_kernel<<<dim3(66, NB), 256, CONV_SMEM>>>(
        w[0], bb[0], w[1], bb[1], w[2], bb[2], w[3], bb[3],
        w[4], bb[4], w[5], bb[5], w[6], bb[6], w[7], bb[7], out);
}

// round 7
// speedup vs baseline: 5.0846x; 5.0846x over previous
#include <cuda_runtime.h>
#include <math.h>
#include <stdint.h>

#define T 1024
#define C 128
#define NB 16
#define LUP 523776          // T*(T-1)/2
#define NOUT 2046           // LUP / 256
#define LEAK 0.2f

// ---------------------------------------------------------------------------
// Device globals (scratch)
// ---------------------------------------------------------------------------
__device__ float g_up[(size_t)NB * LUP];   // packed upper-triangle distances
__device__ float g_xx[NB * T];             // row squared norms

// ---------------------------------------------------------------------------
// Helpers
// ---------------------------------------------------------------------------
__device__ __forceinline__ uint32_t to_tf32(float f) {
    uint32_t r;
    asm("cvt.rna.tf32.f32 %0, %1;" : "=r"(r) : "f"(f));
    return r;
}

__device__ __forceinline__ void mma_tf32(float* d, const uint32_t* a, const uint32_t* b) {
    asm volatile(
        "mma.sync.aligned.m16n8k8.row.col.f32.tf32.tf32.f32 "
        "{%0,%1,%2,%3}, {%4,%5,%6,%7}, {%8,%9}, {%0,%1,%2,%3};"
        : "+f"(d[0]), "+f"(d[1]), "+f"(d[2]), "+f"(d[3])
        : "r"(a[0]), "r"(a[1]), "r"(a[2]), "r"(a[3]),
          "r"(b[0]), "r"(b[1]));
}

__device__ __forceinline__ float lrelu(float v) {
    return fmaxf(v, LEAK * v);
}

// ---------------------------------------------------------------------------
// Kernel 1: xx[b][i] = sum_c x[b][i][c]^2.  One warp per row.
// ---------------------------------------------------------------------------
__global__ __launch_bounds__(256) void xx_kernel(const float* __restrict__ x) {
    int warp = (blockIdx.x * 256 + threadIdx.x) >> 5;
    int lane = threadIdx.x & 31;
    if (warp >= NB * T) return;
    const float4* row = (const float4*)(x + (size_t)warp * C);
    float4 v = row[lane];
    float s = v.x * v.x + v.y * v.y + v.z * v.z + v.w * v.w;
    #pragma unroll
    for (int o = 16; o; o >>= 1) s += __shfl_xor_sync(0xffffffffu, s, o);
    if (lane == 0) g_xx[warp] = s;
}

// ---------------------------------------------------------------------------
// Kernel 2: tf32 mma.sync Gram tiles -> packed sqrt distances.
// (verbatim from round-3 passing build)
// ---------------------------------------------------------------------------
#define AS_STRIDE 132
#define AS_BYTES  (128 * AS_STRIDE * 4)       // 67584
#define DIST_SMEM (2 * AS_BYTES)              // 135168

__global__ __launch_bounds__(256) void dist_kernel(const float* __restrict__ x) {
    extern __shared__ __align__(16) unsigned char sm[];
    uint32_t* As = (uint32_t*)sm;
    uint32_t* Bs = (uint32_t*)(sm + AS_BYTES);

    int tid = threadIdx.x;
    int wid = tid >> 5;
    int lane = tid & 31;
    int grp = lane >> 2;        // 0..7
    int tg  = lane & 3;         // 0..3

    int b = blockIdx.y;
    int t = blockIdx.x;
    int ti = 0, rem = t;
    while (rem >= 8 - ti) { rem -= 8 - ti; ++ti; }
    int tj = ti + rem;
    int i0 = ti * 128, j0 = tj * 128;

    const float* xb = x + (size_t)b * T * C;

    #pragma unroll
    for (int it = 0; it < 16; ++it) {
        int f4 = it * 256 + tid;
        int row = f4 >> 5, c4 = f4 & 31;
        float4 va = *(const float4*)(xb + (size_t)(i0 + row) * C + c4 * 4);
        uint4 ta = make_uint4(to_tf32(va.x), to_tf32(va.y), to_tf32(va.z), to_tf32(va.w));
        *(uint4*)&As[row * AS_STRIDE + c4 * 4] = ta;
        float4 vb = *(const float4*)(xb + (size_t)(j0 + row) * C + c4 * 4);
        uint4 tb = make_uint4(to_tf32(vb.x), to_tf32(vb.y), to_tf32(vb.z), to_tf32(vb.w));
        *(uint4*)&Bs[row * AS_STRIDE + c4 * 4] = tb;
    }
    __syncthreads();

    int warp_m = (wid >> 2) * 64;
    int warp_n = (wid & 3) * 32;

    float acc[4][4][4];
    #pragma unroll
    for (int e = 0; e < 4; ++e)
        #pragma unroll
        for (int f = 0; f < 4; ++f)
            #pragma unroll
            for (int q = 0; q < 4; ++q) acc[e][f][q] = 0.0f;

    int abase = (warp_m + grp) * AS_STRIDE + tg;
    int bbase = (warp_n + grp) * AS_STRIDE + tg;

    #pragma unroll 2
    for (int kb = 0; kb < 128; kb += 8) {
        uint32_t a[4][4], bf[4][2];
        #pragma unroll
        for (int e = 0; e < 4; ++e) {
            int r = abase + 16 * e * AS_STRIDE + kb;
            a[e][0] = As[r];
            a[e][1] = As[r + 8 * AS_STRIDE];
            a[e][2] = As[r + 4];
            a[e][3] = As[r + 8 * AS_STRIDE + 4];
        }
        #pragma unroll
        for (int f = 0; f < 4; ++f) {
            int r = bbase + 8 * f * AS_STRIDE + kb;
            bf[f][0] = Bs[r];
            bf[f][1] = Bs[r + 4];
        }
        #pragma unroll
        for (int e = 0; e < 4; ++e)
            #pragma unroll
            for (int f = 0; f < 4; ++f)
                mma_tf32(acc[e][f], a[e], bf[f]);
    }

    float xi[4][2], xj[4][2];
    #pragma unroll
    for (int e = 0; e < 4; ++e) {
        int il = warp_m + 16 * e + grp;
        xi[e][0] = g_xx[b * T + i0 + il];
        xi[e][1] = g_xx[b * T + i0 + il + 8];
    }
    #pragma unroll
    for (int f = 0; f < 4; ++f) {
        int jl = warp_n + 8 * f + 2 * tg;
        xj[f][0] = g_xx[b * T + j0 + jl];
        xj[f][1] = g_xx[b * T + j0 + jl + 1];
    }

    __syncthreads();
    float* S = (float*)sm;   // 128 x stride-129 staging

    #pragma unroll
    for (int e = 0; e < 4; ++e) {
        int il = warp_m + 16 * e + grp;
        #pragma unroll
        for (int f = 0; f < 4; ++f) {
            int jl = warp_n + 8 * f + 2 * tg;
            float d00 = fmaf(-2.0f, acc[e][f][0], xi[e][0] + xj[f][0]);
            float d01 = fmaf(-2.0f, acc[e][f][1], xi[e][0] + xj[f][1]);
            float d10 = fmaf(-2.0f, acc[e][f][2], xi[e][1] + xj[f][0]);
            float d11 = fmaf(-2.0f, acc[e][f][3], xi[e][1] + xj[f][1]);
            S[il * 129 + jl]           = sqrtf(fmaxf(d00, 0.0f));
            S[il * 129 + jl + 1]       = sqrtf(fmaxf(d01, 0.0f));
            S[(il + 8) * 129 + jl]     = sqrtf(fmaxf(d10, 0.0f));
            S[(il + 8) * 129 + jl + 1] = sqrtf(fmaxf(d11, 0.0f));
        }
    }
    __syncthreads();

    {
        long bbase2 = (long)b * LUP;
        #pragma unroll
        for (int q = tid; q < 128 * 128; q += 256) {
            int m = q >> 7, jj = q & 127;
            int i2 = i0 + m, j2 = j0 + jj;
            if (j2 > i2) {
                long ro = (long)i2 * (2 * T - 1 - i2) / 2 - i2 - 1;
                g_up[bbase2 + ro + j2] = S[m * 129 + jj];
            }
        }
    }
}

// ---------------------------------------------------------------------------
// Kernel 3 (v4): R1 conv structure with register-resident weights.
// 6 final outputs per block (2046 = 341 * 6), 1536 inputs, 40KB static smem.
// Each thread's output channel c = tid&7 is CONSTANT -> per layer, its 16
// weights are hoisted into 4 float4 registers (zero weight-LDS in the inner
// loop). Inputs read as 4x LDS.128 (8-lane broadcast groups, conflict-free).
// wgt layout: [0,16) w0; [16,24) b0; [24,792) w1..w6 (128 each);
//             [792,840) b1..b6 (8 each); [840,856) w7; [856] b7.
// ---------------------------------------------------------------------------
__global__ __launch_bounds__(256) void conv_kernel(
    const float* __restrict__ w0, const float* __restrict__ b0,
    const float* __restrict__ w1, const float* __restrict__ b1,
    const float* __restrict__ w2, const float* __restrict__ b2,
    const float* __restrict__ w3, const float* __restrict__ b3,
    const float* __restrict__ w4, const float* __restrict__ b4,
    const float* __restrict__ w5, const float* __restrict__ b5,
    const float* __restrict__ w6, const float* __restrict__ b6,
    const float* __restrict__ w7, const float* __restrict__ b7,
    float* __restrict__ out)
{
    __shared__ float A[6144];    // up to 8ch x 768, channel-inner
    __shared__ float Bu[3072];   // up to 8ch x 384; also holds the 1536 inputs
    __shared__ float wgt[860];

    int tid = threadIdx.x;
    int c   = tid & 7;           // fixed output channel for this thread
    int b   = blockIdx.y;
    int blk = blockIdx.x;        // 0..340

    // ---- stage weights into shared ----
    if (tid < 128) {
        wgt[ 24 + tid] = w1[tid];
        wgt[152 + tid] = w2[tid];
        wgt[280 + tid] = w3[tid];
        wgt[408 + tid] = w4[tid];
        wgt[536 + tid] = w5[tid];
        wgt[664 + tid] = w6[tid];
    } else {
        int u = tid - 128;
        if (u < 16)       wgt[u]            = w0[u];
        else if (u < 24)  wgt[u]            = b0[u - 16];
        else if (u < 32)  wgt[792 + (u-24)] = b1[u-24];
        else if (u < 40)  wgt[800 + (u-32)] = b2[u-32];
        else if (u < 48)  wgt[808 + (u-40)] = b3[u-40];
        else if (u < 56)  wgt[816 + (u-48)] = b4[u-48];
        else if (u < 64)  wgt[824 + (u-56)] = b5[u-56];
        else if (u < 72)  wgt[832 + (u-64)] = b6[u-64];
        else if (u < 88)  wgt[840 + (u-72)] = w7[u-72];
        else if (u == 88) wgt[856]          = b7[0];
    }

    // ---- load 1536 contiguous packed distances into Bu (float4) ----
    {
        const float4* src = (const float4*)(g_up + (size_t)b * LUP + (size_t)blk * 1536);
        float4* dst = (float4*)Bu;
        #pragma unroll
        for (int q = tid; q < 384; q += 256) dst[q] = src[q];
    }
    __syncthreads();

    // ---- layer 0: 1ch x 1536 -> 8ch x 768 (register weights) ----
    {
        float wa = wgt[2 * c], wb2 = wgt[2 * c + 1], bc = wgt[16 + c];
        #pragma unroll
        for (int it = 0; it < 24; ++it) {
            int q = it * 256 + tid;          // 0..6143
            int p = q >> 3;                  // position; (q&7)==c
            float v = fmaf(wa, Bu[2 * p], fmaf(wb2, Bu[2 * p + 1], bc));
            A[p * 8 + c] = lrelu(v);
        }
    }
    __syncthreads();

    // ---- layers 1..6: 8ch -> 8ch, halving (register weights, LDS.128 in) ----
    float* src = A;
    float* dst = Bu;
    int len = 768;
    #pragma unroll 1
    for (int l = 0; l < 6; ++l) {
        int olen = len >> 1;
        const float4* Wc = (const float4*)(wgt + 24 + l * 128 + c * 16);
        float4 wrA = Wc[0], wrB = Wc[1], wrC = Wc[2], wrD = Wc[3];
        float bc = wgt[792 + l * 8 + c];

        for (int q = tid; q < 8 * olen; q += 256) {
            int p = q >> 3;                  // (q&7)==c
            const float4* s4 = (const float4*)(src + 16 * p);
            float4 a0 = s4[0], a1 = s4[1], a2 = s4[2], a3 = s4[3];
            float acc = bc;
            acc = fmaf(wrA.x, a0.x, acc); acc = fmaf(wrA.y, a2.x, acc);
            acc = fmaf(wrA.z, a0.y, acc); acc = fmaf(wrA.w, a2.y, acc);
            acc = fmaf(wrB.x, a0.z, acc); acc = fmaf(wrB.y, a2.z, acc);
            acc = fmaf(wrB.z, a0.w, acc); acc = fmaf(wrB.w, a2.w, acc);
            acc = fmaf(wrC.x, a1.x, acc); acc = fmaf(wrC.y, a3.x, acc);
            acc = fmaf(wrC.z, a1.y, acc); acc = fmaf(wrC.w, a3.y, acc);
            acc = fmaf(wrD.x, a1.z, acc); acc = fmaf(wrD.y, a3.z, acc);
            acc = fmaf(wrD.z, a1.w, acc); acc = fmaf(wrD.w, a3.w, acc);
            dst[p * 8 + c] = lrelu(acc);
        }
        __syncthreads();
        float* tmp = src; src = dst; dst = tmp;
        len = olen;
    }

    // ---- layer 7: 8ch x 12 -> 1ch x 6 (no activation) ----
    if (tid < 6) {
        const float* s0 = src + 16 * tid;
        const float4* Wc = (const float4*)(wgt + 840);
        float4 wa = Wc[0], wb = Wc[1], wc2 = Wc[2], wd = Wc[3];
        float acc = wgt[856];
        acc = fmaf(wa.x,  s0[0], acc); acc = fmaf(wa.y,  s0[8],  acc);
        acc = fmaf(wa.z,  s0[1], acc); acc = fmaf(wa.w,  s0[9],  acc);
        acc = fmaf(wb.x,  s0[2], acc); acc = fmaf(wb.y,  s0[10], acc);
        acc = fmaf(wb.z,  s0[3], acc); acc = fmaf(wb.w,  s0[11], acc);
        acc = fmaf(wc2.x, s0[4], acc); acc = fmaf(wc2.y, s0[12], acc);
        acc = fmaf(wc2.z, s0[5], acc); acc = fmaf(wc2.w, s0[13], acc);
        acc = fmaf(wd.x,  s0[6], acc); acc = fmaf(wd.y,  s0[14], acc);
        acc = fmaf(wd.z,  s0[7], acc); acc = fmaf(wd.w,  s0[15], acc);
        out[b * NOUT + blk * 6 + tid] = acc;
    }
}

// ---------------------------------------------------------------------------
extern "C" void kernel_launch(void* const* d_in, const int* in_sizes, int n_in,
                              void* d_out, int out_size) {
    const float* x = (const float*)d_in[0];
    const float* w[8];
    const float* bb[8];
    for (int i = 0; i < 8; ++i) {
        w[i]  = (const float*)d_in[1 + 2 * i];
        bb[i] = (const float*)d_in[2 + 2 * i];
    }
    float* out = (float*)d_out;

    cudaFuncSetAttribute(dist_kernel,
                         cudaFuncAttributeMaxDynamicSharedMemorySize, DIST_SMEM);

    xx_kernel<<<(NB * T) / 8, 256>>>(x);
    dist_kernel<<<dim3(36, NB), 256, DIST_SMEM>>>(x);
    conv_kernel<<<dim3(341, NB), 256>>>(
        w[0], bb[0], w[1], bb[1], w[2], bb[2], w[3], bb[3],
        w[4], bb[4], w[5], bb[5], w[6], bb[6], w[7], bb[7], out);
}

// round 8
// speedup vs baseline: 5.2432x; 1.0312x over previous
#include <cuda_runtime.h>
#include <cuda_fp16.h>
#include <math.h>
#include <stdint.h>

#define T 1024
#define C 128
#define NB 16
#define LUP 523776          // T*(T-1)/2
#define NOUT 2046           // LUP / 256
#define LEAK 0.2f

// ---------------------------------------------------------------------------
// Device globals (scratch)
// ---------------------------------------------------------------------------
__device__ __half g_up[(size_t)NB * LUP];  // packed upper-triangle distances (fp16)
__device__ float g_xx[NB * T];             // row squared norms

// ---------------------------------------------------------------------------
// Helpers
// ---------------------------------------------------------------------------
__device__ __forceinline__ uint32_t to_tf32(float f) {
    uint32_t r;
    asm("cvt.rna.tf32.f32 %0, %1;" : "=r"(r) : "f"(f));
    return r;
}

__device__ __forceinline__ void mma_tf32(float* d, const uint32_t* a, const uint32_t* b) {
    asm volatile(
        "mma.sync.aligned.m16n8k8.row.col.f32.tf32.tf32.f32 "
        "{%0,%1,%2,%3}, {%4,%5,%6,%7}, {%8,%9}, {%0,%1,%2,%3};"
        : "+f"(d[0]), "+f"(d[1]), "+f"(d[2]), "+f"(d[3])
        : "r"(a[0]), "r"(a[1]), "r"(a[2]), "r"(a[3]),
          "r"(b[0]), "r"(b[1]));
}

__device__ __forceinline__ float lrelu(float v) {
    return fmaxf(v, LEAK * v);
}

__device__ __forceinline__ float fsqrt_approx(float v) {
    float r;
    asm("sqrt.approx.f32 %0, %1;" : "=f"(r) : "f"(v));
    return r;
}

// ---------------------------------------------------------------------------
// Kernel 1: xx[b][i] = sum_c x[b][i][c]^2.  One warp per row.
// ---------------------------------------------------------------------------
__global__ __launch_bounds__(256) void xx_kernel(const float* __restrict__ x) {
    int warp = (blockIdx.x * 256 + threadIdx.x) >> 5;
    int lane = threadIdx.x & 31;
    if (warp >= NB * T) return;
    const float4* row = (const float4*)(x + (size_t)warp * C);
    float4 v = row[lane];
    float s = v.x * v.x + v.y * v.y + v.z * v.z + v.w * v.w;
    #pragma unroll
    for (int o = 16; o; o >>= 1) s += __shfl_xor_sync(0xffffffffu, s, o);
    if (lane == 0) g_xx[warp] = s;
}

// ---------------------------------------------------------------------------
// Kernel 2: tf32 mma.sync Gram tiles -> packed fp16 sqrt distances.
// Same structure as the 156.6us build; epilogue stages half2, stores half.
// ---------------------------------------------------------------------------
#define AS_STRIDE 132
#define AS_BYTES  (128 * AS_STRIDE * 4)       // 67584
#define DIST_SMEM (2 * AS_BYTES)              // 135168
#define HS_STRIDE 130                          // half staging stride (even)

__global__ __launch_bounds__(256) void dist_kernel(const float* __restrict__ x) {
    extern __shared__ __align__(16) unsigned char sm[];
    uint32_t* As = (uint32_t*)sm;
    uint32_t* Bs = (uint32_t*)(sm + AS_BYTES);

    int tid = threadIdx.x;
    int wid = tid >> 5;
    int lane = tid & 31;
    int grp = lane >> 2;        // 0..7
    int tg  = lane & 3;         // 0..3

    int b = blockIdx.y;
    int t = blockIdx.x;
    int ti = 0, rem = t;
    while (rem >= 8 - ti) { rem -= 8 - ti; ++ti; }
    int tj = ti + rem;
    int i0 = ti * 128, j0 = tj * 128;

    const float* xb = x + (size_t)b * T * C;

    #pragma unroll
    for (int it = 0; it < 16; ++it) {
        int f4 = it * 256 + tid;
        int row = f4 >> 5, c4 = f4 & 31;
        float4 va = *(const float4*)(xb + (size_t)(i0 + row) * C + c4 * 4);
        uint4 ta = make_uint4(to_tf32(va.x), to_tf32(va.y), to_tf32(va.z), to_tf32(va.w));
        *(uint4*)&As[row * AS_STRIDE + c4 * 4] = ta;
        float4 vb = *(const float4*)(xb + (size_t)(j0 + row) * C + c4 * 4);
        uint4 tb = make_uint4(to_tf32(vb.x), to_tf32(vb.y), to_tf32(vb.z), to_tf32(vb.w));
        *(uint4*)&Bs[row * AS_STRIDE + c4 * 4] = tb;
    }
    __syncthreads();

    int warp_m = (wid >> 2) * 64;
    int warp_n = (wid & 3) * 32;

    float acc[4][4][4];
    #pragma unroll
    for (int e = 0; e < 4; ++e)
        #pragma unroll
        for (int f = 0; f < 4; ++f)
            #pragma unroll
            for (int q = 0; q < 4; ++q) acc[e][f][q] = 0.0f;

    int abase = (warp_m + grp) * AS_STRIDE + tg;
    int bbase = (warp_n + grp) * AS_STRIDE + tg;

    #pragma unroll 2
    for (int kb = 0; kb < 128; kb += 8) {
        uint32_t a[4][4], bf[4][2];
        #pragma unroll
        for (int e = 0; e < 4; ++e) {
            int r = abase + 16 * e * AS_STRIDE + kb;
            a[e][0] = As[r];
            a[e][1] = As[r + 8 * AS_STRIDE];
            a[e][2] = As[r + 4];
            a[e][3] = As[r + 8 * AS_STRIDE + 4];
        }
        #pragma unroll
        for (int f = 0; f < 4; ++f) {
            int r = bbase + 8 * f * AS_STRIDE + kb;
            bf[f][0] = Bs[r];
            bf[f][1] = Bs[r + 4];
        }
        #pragma unroll
        for (int e = 0; e < 4; ++e)
            #pragma unroll
            for (int f = 0; f < 4; ++f)
                mma_tf32(acc[e][f], a[e], bf[f]);
    }

    float xi[4][2], xj[4][2];
    #pragma unroll
    for (int e = 0; e < 4; ++e) {
        int il = warp_m + 16 * e + grp;
        xi[e][0] = g_xx[b * T + i0 + il];
        xi[e][1] = g_xx[b * T + i0 + il + 8];
    }
    #pragma unroll
    for (int f = 0; f < 4; ++f) {
        int jl = warp_n + 8 * f + 2 * tg;
        xj[f][0] = g_xx[b * T + j0 + jl];
        xj[f][1] = g_xx[b * T + j0 + jl + 1];
    }

    __syncthreads();
    __half* S = (__half*)sm;   // 128 x stride-130 half staging

    #pragma unroll
    for (int e = 0; e < 4; ++e) {
        int il = warp_m + 16 * e + grp;
        #pragma unroll
        for (int f = 0; f < 4; ++f) {
            int jl = warp_n + 8 * f + 2 * tg;   // even
            float d00 = fmaf(-2.0f, acc[e][f][0], xi[e][0] + xj[f][0]);
            float d01 = fmaf(-2.0f, acc[e][f][1], xi[e][0] + xj[f][1]);
            float d10 = fmaf(-2.0f, acc[e][f][2], xi[e][1] + xj[f][0]);
            float d11 = fmaf(-2.0f, acc[e][f][3], xi[e][1] + xj[f][1]);
            float s00 = fsqrt_approx(fmaxf(d00, 0.0f));
            float s01 = fsqrt_approx(fmaxf(d01, 0.0f));
            float s10 = fsqrt_approx(fmaxf(d10, 0.0f));
            float s11 = fsqrt_approx(fmaxf(d11, 0.0f));
            *(__half2*)&S[il * HS_STRIDE + jl]       = __floats2half2_rn(s00, s01);
            *(__half2*)&S[(il + 8) * HS_STRIDE + jl] = __floats2half2_rn(s10, s11);
        }
    }
    __syncthreads();

    // coalesced packed-triangle store (fp16)
    {
        long bbase2 = (long)b * LUP;
        #pragma unroll
        for (int q = tid; q < 128 * 128; q += 256) {
            int m = q >> 7, jj = q & 127;
            int i2 = i0 + m, j2 = j0 + jj;
            if (j2 > i2) {
                long ro = (long)i2 * (2 * T - 1 - i2) / 2 - i2 - 1;
                g_up[bbase2 + ro + j2] = S[m * HS_STRIDE + jj];
            }
        }
    }
}

// ---------------------------------------------------------------------------
// Kernel 3: conv stack (register-weight v4 from the 156.6us build),
// input path switched to fp16 (half2 broadcast reads in L0).
// ---------------------------------------------------------------------------
__global__ __launch_bounds__(256) void conv_kernel(
    const float* __restrict__ w0, const float* __restrict__ b0,
    const float* __restrict__ w1, const float* __restrict__ b1,
    const float* __restrict__ w2, const float* __restrict__ b2,
    const float* __restrict__ w3, const float* __restrict__ b3,
    const float* __restrict__ w4, const float* __restrict__ b4,
    const float* __restrict__ w5, const float* __restrict__ b5,
    const float* __restrict__ w6, const float* __restrict__ b6,
    const float* __restrict__ w7, const float* __restrict__ b7,
    float* __restrict__ out)
{
    __shared__ float A[6144];       // 8ch x 768, channel-inner
    __shared__ float Bu[3072];      // ping-pong buffer
    __shared__ __half BuH[1536];    // fp16 input staging
    __shared__ float wgt[860];

    int tid = threadIdx.x;
    int c   = tid & 7;
    int b   = blockIdx.y;
    int blk = blockIdx.x;        // 0..340

    // ---- stage weights ----
    if (tid < 128) {
        wgt[ 24 + tid] = w1[tid];
        wgt[152 + tid] = w2[tid];
        wgt[280 + tid] = w3[tid];
        wgt[408 + tid] = w4[tid];
        wgt[536 + tid] = w5[tid];
        wgt[664 + tid] = w6[tid];
    } else {
        int u = tid - 128;
        if (u < 16)       wgt[u]            = w0[u];
        else if (u < 24)  wgt[u]            = b0[u - 16];
        else if (u < 32)  wgt[792 + (u-24)] = b1[u-24];
        else if (u < 40)  wgt[800 + (u-32)] = b2[u-32];
        else if (u < 48)  wgt[808 + (u-40)] = b3[u-40];
        else if (u < 56)  wgt[816 + (u-48)] = b4[u-48];
        else if (u < 64)  wgt[824 + (u-56)] = b5[u-56];
        else if (u < 72)  wgt[832 + (u-64)] = b6[u-64];
        else if (u < 88)  wgt[840 + (u-72)] = w7[u-72];
        else if (u == 88) wgt[856]          = b7[0];
    }

    // ---- load 1536 contiguous fp16 distances (3KB, uint4) ----
    {
        const uint4* src = (const uint4*)(g_up + (size_t)b * LUP + (size_t)blk * 1536);
        uint4* dst = (uint4*)BuH;
        if (tid < 192) dst[tid] = src[tid];
    }
    __syncthreads();

    // ---- layer 0: 1ch x 1536 -> 8ch x 768 (half2 broadcast in) ----
    {
        float wa = wgt[2 * c], wb2 = wgt[2 * c + 1], bc = wgt[16 + c];
        const __half2* B2 = (const __half2*)BuH;
        #pragma unroll
        for (int it = 0; it < 24; ++it) {
            int q = it * 256 + tid;          // 0..6143
            int p = q >> 3;                  // (q&7)==c
            float2 u = __half22float2(B2[p]);
            float v = fmaf(wa, u.x, fmaf(wb2, u.y, bc));
            A[p * 8 + c] = lrelu(v);
        }
    }
    __syncthreads();

    // ---- layers 1..6: 8ch -> 8ch, halving (register weights, LDS.128 in) ----
    float* src = A;
    float* dst = Bu;
    int len = 768;
    #pragma unroll 1
    for (int l = 0; l < 6; ++l) {
        int olen = len >> 1;
        const float4* Wc = (const float4*)(wgt + 24 + l * 128 + c * 16);
        float4 wrA = Wc[0], wrB = Wc[1], wrC = Wc[2], wrD = Wc[3];
        float bc = wgt[792 + l * 8 + c];

        for (int q = tid; q < 8 * olen; q += 256) {
            int p = q >> 3;                  // (q&7)==c
            const float4* s4 = (const float4*)(src + 16 * p);
            float4 a0 = s4[0], a1 = s4[1], a2 = s4[2], a3 = s4[3];
            float acc = bc;
            acc = fmaf(wrA.x, a0.x, acc); acc = fmaf(wrA.y, a2.x, acc);
            acc = fmaf(wrA.z, a0.y, acc); acc = fmaf(wrA.w, a2.y, acc);
            acc = fmaf(wrB.x, a0.z, acc); acc = fmaf(wrB.y, a2.z, acc);
            acc = fmaf(wrB.z, a0.w, acc); acc = fmaf(wrB.w, a2.w, acc);
            acc = fmaf(wrC.x, a1.x, acc); acc = fmaf(wrC.y, a3.x, acc);
            acc = fmaf(wrC.z, a1.y, acc); acc = fmaf(wrC.w, a3.y, acc);
            acc = fmaf(wrD.x, a1.z, acc); acc = fmaf(wrD.y, a3.z, acc);
            acc = fmaf(wrD.z, a1.w, acc); acc = fmaf(wrD.w, a3.w, acc);
            dst[p * 8 + c] = lrelu(acc);
        }
        __syncthreads();
        float* tmp = src; src = dst; dst = tmp;
        len = olen;
    }

    // ---- layer 7: 8ch x 12 -> 1ch x 6 (no activation) ----
    if (tid < 6) {
        const float* s0 = src + 16 * tid;
        const float4* Wc = (const float4*)(wgt + 840);
        float4 wa = Wc[0], wb = Wc[1], wc2 = Wc[2], wd = Wc[3];
        float acc = wgt[856];
        acc = fmaf(wa.x,  s0[0], acc); acc = fmaf(wa.y,  s0[8],  acc);
        acc = fmaf(wa.z,  s0[1], acc); acc = fmaf(wa.w,  s0[9],  acc);
        acc = fmaf(wb.x,  s0[2], acc); acc = fmaf(wb.y,  s0[10], acc);
        acc = fmaf(wb.z,  s0[3], acc); acc = fmaf(wb.w,  s0[11], acc);
        acc = fmaf(wc2.x, s0[4], acc); acc = fmaf(wc2.y, s0[12], acc);
        acc = fmaf(wc2.z, s0[5], acc); acc = fmaf(wc2.w, s0[13], acc);
        acc = fmaf(wd.x,  s0[6], acc); acc = fmaf(wd.y,  s0[14], acc);
        acc = fmaf(wd.z,  s0[7], acc); acc = fmaf(wd.w,  s0[15], acc);
        out[b * NOUT + blk * 6 + tid] = acc;
    }
}

// ---------------------------------------------------------------------------
extern "C" void kernel_launch(void* const* d_in, const int* in_sizes, int n_in,
                              void* d_out, int out_size) {
    const float* x = (const float*)d_in[0];
    const float* w[8];
    const float* bb[8];
    for (int i = 0; i < 8; ++i) {
        w[i]  = (const float*)d_in[1 + 2 * i];
        bb[i] = (const float*)d_in[2 + 2 * i];
    }
    float* out = (float*)d_out;

    cudaFuncSetAttribute(dist_kernel,
                         cudaFuncAttributeMaxDynamicSharedMemorySize, DIST_SMEM);

    xx_kernel<<<(NB * T) / 8, 256>>>(x);
    dist_kernel<<<dim3(36, NB), 256, DIST_SMEM>>>(x);
    conv_kernel<<<dim3(341, NB), 256>>>(
        w[0], bb[0], w[1], bb[1], w[2], bb[2], w[3], bb[3],
        w[4], bb[4], w[5], bb[5], w[6], bb[6], w[7], bb[7], out);
}